// round 2
// baseline (speedup 1.0000x reference)
#include <cuda_runtime.h>
#include <cuda_bf16.h>

// ---------------------------------------------------------------------------
// Problem constants: B=4, L=8192, D=768, K=24, NFFT=16384.
// Math: out[t] = 2 * sum_{j even, j<=t} v[j] * u[t-j]
//   => two length-4096 causal convs with v_e[i]=v[2i], fused into ONE complex
//      FFT of size 8192 via z[k] = u[2k] + i*u[2k+1].
// ---------------------------------------------------------------------------

#define BATCH 4
#define SEQ   8192
#define DIM   768
#define NK    24
#define NC    8192            // complex FFT length
#define HALF  4096

// padded/skewed shared-memory indexing for the FFT (kills stride-8 conflicts)
#define SMX(i) ((i) + ((i) >> 4))
#define FFT_BUF 8704          // SMX(8191)=8702 -> 8704 float2 per buffer
#define FFT_SMEM_BYTES (2 * FFT_BUF * (int)sizeof(float2))   // 139264

// Scratch (device globals: no allocation allowed anywhere)
__device__ float  g_XT[(size_t)BATCH * DIM * SEQ];   // (B, D, L) fp32, ~100MB, used in place
__device__ float2 g_VS[(size_t)DIM * NC];            // filter spectra, ~50MB

// ---------------------------------------------------------------------------
// complex helpers
// ---------------------------------------------------------------------------
__device__ __forceinline__ float2 cmul(float2 a, float2 b) {
    return make_float2(a.x * b.x - a.y * b.y, a.x * b.y + a.y * b.x);
}

template<int DIR>   // DIR = -1 forward, +1 inverse (unnormalized)
__device__ __forceinline__ void dft4(float2& a, float2& b, float2& c, float2& d) {
    float2 t0 = make_float2(a.x + c.x, a.y + c.y);
    float2 t1 = make_float2(a.x - c.x, a.y - c.y);
    float2 t2 = make_float2(b.x + d.x, b.y + d.y);
    float2 t3 = make_float2(b.x - d.x, b.y - d.y);
    a = make_float2(t0.x + t2.x, t0.y + t2.y);
    c = make_float2(t0.x - t2.x, t0.y - t2.y);
    if (DIR == -1) {
        b = make_float2(t1.x + t3.y, t1.y - t3.x);   // t1 - i t3
        d = make_float2(t1.x - t3.y, t1.y + t3.x);   // t1 + i t3
    } else {
        b = make_float2(t1.x - t3.y, t1.y + t3.x);
        d = make_float2(t1.x + t3.y, t1.y - t3.x);
    }
}

template<int DIR>
__device__ __forceinline__ void dft8(float2 v[8]) {
    const float S = 0.7071067811865476f;
    float2 e0 = v[0], e1 = v[2], e2 = v[4], e3 = v[6];
    float2 o0 = v[1], o1 = v[3], o2 = v[5], o3 = v[7];
    dft4<DIR>(e0, e1, e2, e3);
    dft4<DIR>(o0, o1, o2, o3);
    // twiddle odd part by w8^m, w8 = e^{DIR*i*pi/4}
    o1 = cmul(o1, make_float2(S, (float)DIR * S));
    o2 = (DIR == -1) ? make_float2(o2.y, -o2.x) : make_float2(-o2.y, o2.x);
    o3 = cmul(o3, make_float2(-S, (float)DIR * S));
    v[0] = make_float2(e0.x + o0.x, e0.y + o0.y); v[4] = make_float2(e0.x - o0.x, e0.y - o0.y);
    v[1] = make_float2(e1.x + o1.x, e1.y + o1.y); v[5] = make_float2(e1.x - o1.x, e1.y - o1.y);
    v[2] = make_float2(e2.x + o2.x, e2.y + o2.y); v[6] = make_float2(e2.x - o2.x, e2.y - o2.y);
    v[3] = make_float2(e3.x + o3.x, e3.y + o3.y); v[7] = make_float2(e3.x - o3.x, e3.y - o3.y);
}

// Stockham autosort FFT, N=8192 = 8^4 * 2, 512 threads, ping-pong buffers.
// Input in src, output in dst. Caller must have synced before entry.
template<int DIR>
__device__ __forceinline__ void fft8192(float2* src, float2* dst, int tid) {
    float2* s = src;
    float2* d = dst;
    int Ns = 1;
    #pragma unroll
    for (int st = 0; st < 4; st++) {
        const float angc = (float)DIR * 6.283185307179586f / (8.0f * (float)Ns);
        #pragma unroll
        for (int it = 0; it < 2; it++) {
            int j  = tid + it * 512;            // 0..1023
            int jm = j & (Ns - 1);
            float ang = angc * (float)jm;
            float c, sn;
            __sincosf(ang, &sn, &c);
            float2 w1 = make_float2(c, sn);
            float2 v[8];
            v[0] = s[SMX(j)];
            float2 wr = w1;
            #pragma unroll
            for (int r = 1; r < 8; r++) {
                v[r] = cmul(s[SMX(j + r * 1024)], wr);
                wr = cmul(wr, w1);
            }
            dft8<DIR>(v);
            int base = ((j & ~(Ns - 1)) << 3) + jm;   // (j/Ns)*Ns*8 + j%Ns
            #pragma unroll
            for (int r = 0; r < 8; r++) d[SMX(base + r * Ns)] = v[r];
        }
        __syncthreads();
        float2* t = s; s = d; d = t;
        Ns <<= 3;
    }
    // final radix-2 stage, Ns = 4096
    const float angc2 = (float)DIR * 6.283185307179586f / 8192.0f;
    #pragma unroll
    for (int it = 0; it < 8; it++) {
        int j = tid + it * 512;                 // 0..4095
        float c, sn;
        __sincosf(angc2 * (float)j, &sn, &c);
        float2 v0 = s[SMX(j)];
        float2 v1 = cmul(s[SMX(j + 4096)], make_float2(c, sn));
        d[SMX(j)]        = make_float2(v0.x + v1.x, v0.y + v1.y);
        d[SMX(j + 4096)] = make_float2(v0.x - v1.x, v0.y - v1.y);
    }
    __syncthreads();
}

// ---------------------------------------------------------------------------
// Kernel 1: filter prep. One CTA per output channel d.
//   v_e[i] = sum_k phi[2i,k] * M_filters[k,d],  VS[d] = FFT(v_e * 2/8192)
// ---------------------------------------------------------------------------
__global__ void __launch_bounds__(512, 1)
filter_kernel(const float* __restrict__ phi, const float* __restrict__ Mf) {
    extern __shared__ float2 fb[];
    float2* A  = fb;
    float2* Bu = fb + FFT_BUF;
    __shared__ float mf[NK];

    const int tid = threadIdx.x;
    const int d   = blockIdx.x;
    if (tid < NK) mf[tid] = Mf[tid * DIM + d];
    __syncthreads();

    const float sc = 2.0f / 8192.0f;
    #pragma unroll 1
    for (int it = 0; it < 16; it++) {
        int i = tid + it * 512;
        float s = 0.0f;
        if (i < HALF) {
            const float* pr = phi + (size_t)i * (2 * NK);   // row 2i
            #pragma unroll
            for (int k = 0; k < NK; k++) s += pr[k] * mf[k];
        }
        A[SMX(i)] = make_float2(s * sc, 0.0f);
    }
    __syncthreads();

    fft8192<-1>(A, Bu, tid);

    float2* vsd = g_VS + ((size_t)d << 13);
    #pragma unroll 1
    for (int it = 0; it < 16; it++) {
        int i = tid + it * 512;
        vsd[i] = Bu[SMX(i)];
    }
}

// ---------------------------------------------------------------------------
// Kernel 2: GEMM  u = x @ M_inputs, written TRANSPOSED into g_XT[b,d,l].
// C tile 128(M=l) x 128(N=d), K-chunks of 16, double-buffered smem,
// inner product on packed fma.rn.f32x2.
// ---------------------------------------------------------------------------
__device__ __forceinline__ unsigned long long pk2(float lo, float hi) {
    unsigned long long r;
    asm("mov.b64 %0, {%1, %2};" : "=l"(r) : "f"(lo), "f"(hi));
    return r;
}
__device__ __forceinline__ unsigned long long fma2(unsigned long long a,
                                                   unsigned long long b,
                                                   unsigned long long c) {
    unsigned long long d;
    asm("fma.rn.f32x2 %0, %1, %2, %3;" : "=l"(d) : "l"(a), "l"(b), "l"(c));
    return d;
}
__device__ __forceinline__ void upk2(unsigned long long v, float& lo, float& hi) {
    asm("mov.b64 {%0, %1}, %2;" : "=f"(lo), "=f"(hi) : "l"(v));
}

__global__ void __launch_bounds__(256, 1)
gemm_kernel(const float* __restrict__ X, const float* __restrict__ Mi) {
    __shared__ float As[2][16][132];
    __shared__ float Bs[2][16][132];

    const int tid = threadIdx.x;
    const int tx  = tid & 15;          // col group (8 cols each)
    const int ty  = tid >> 4;          // row group (8 rows each)
    const int n0  = blockIdx.x * 128;
    const int l0  = blockIdx.y * 128;

    const float* Ab = X  + (size_t)l0 * DIM;
    const float* Bb = Mi + n0;

    float4 ra[2], rb[2];

    // prologue: load chunk 0
    {
        #pragma unroll
        for (int u = 0; u < 2; u++) {
            int i = tid + u * 256;
            ra[u] = *(const float4*)(Ab + (size_t)(i >> 2) * DIM + (i & 3) * 4);
            rb[u] = *(const float4*)(Bb + (size_t)(i >> 5) * DIM + (i & 31) * 4);
        }
        #pragma unroll
        for (int u = 0; u < 2; u++) {
            int i = tid + u * 256;
            As[0][(i & 3) * 4 + 0][i >> 2] = ra[u].x;
            As[0][(i & 3) * 4 + 1][i >> 2] = ra[u].y;
            As[0][(i & 3) * 4 + 2][i >> 2] = ra[u].z;
            As[0][(i & 3) * 4 + 3][i >> 2] = ra[u].w;
            *(float4*)&Bs[0][i >> 5][(i & 31) * 4] = rb[u];
        }
    }
    __syncthreads();

    unsigned long long acc[8][4];
    #pragma unroll
    for (int r = 0; r < 8; r++)
        #pragma unroll
        for (int j = 0; j < 4; j++) acc[r][j] = 0ull;

    #pragma unroll 1
    for (int kc = 0; kc < 48; kc++) {
        if (kc < 47) {
            #pragma unroll
            for (int u = 0; u < 2; u++) {
                int i = tid + u * 256;
                ra[u] = *(const float4*)(Ab + (size_t)(i >> 2) * DIM + (kc + 1) * 16 + (i & 3) * 4);
                rb[u] = *(const float4*)(Bb + (size_t)((kc + 1) * 16 + (i >> 5)) * DIM + (i & 31) * 4);
            }
        }
        const int bf = kc & 1;
        #pragma unroll
        for (int kk = 0; kk < 16; kk++) {
            float4 a0 = *(const float4*)&As[bf][kk][ty * 8];
            float4 a1 = *(const float4*)&As[bf][kk][ty * 8 + 4];
            float4 b0 = *(const float4*)&Bs[bf][kk][tx * 8];
            float4 b1 = *(const float4*)&Bs[bf][kk][tx * 8 + 4];
            unsigned long long bp[4] = { pk2(b0.x, b0.y), pk2(b0.z, b0.w),
                                         pk2(b1.x, b1.y), pk2(b1.z, b1.w) };
            float av[8] = {a0.x, a0.y, a0.z, a0.w, a1.x, a1.y, a1.z, a1.w};
            #pragma unroll
            for (int r = 0; r < 8; r++) {
                unsigned long long ap = pk2(av[r], av[r]);
                #pragma unroll
                for (int jp = 0; jp < 4; jp++) acc[r][jp] = fma2(ap, bp[jp], acc[r][jp]);
            }
        }
        if (kc < 47) {
            const int nb = bf ^ 1;
            #pragma unroll
            for (int u = 0; u < 2; u++) {
                int i = tid + u * 256;
                As[nb][(i & 3) * 4 + 0][i >> 2] = ra[u].x;
                As[nb][(i & 3) * 4 + 1][i >> 2] = ra[u].y;
                As[nb][(i & 3) * 4 + 2][i >> 2] = ra[u].z;
                As[nb][(i & 3) * 4 + 3][i >> 2] = ra[u].w;
                *(float4*)&Bs[nb][i >> 5][(i & 31) * 4] = rb[u];
            }
            __syncthreads();
        }
    }

    // epilogue: write transposed -> g_XT[b, d, l], contiguous along l
    const int b    = l0 >> 13;          // l0 / 8192 (tiles never straddle b)
    const int lloc = l0 & (SEQ - 1);
    #pragma unroll
    for (int j = 0; j < 8; j++) {
        const int jp = j >> 1;
        float vals[8];
        #pragma unroll
        for (int r = 0; r < 8; r++) {
            float lo, hi;
            upk2(acc[r][jp], lo, hi);
            vals[r] = (j & 1) ? hi : lo;
        }
        const int d = n0 + tx * 8 + j;
        float* dst = g_XT + (((size_t)(b * DIM + d)) << 13) + lloc + ty * 8;
        *(float4*)(dst)     = make_float4(vals[0], vals[1], vals[2], vals[3]);
        *(float4*)(dst + 4) = make_float4(vals[4], vals[5], vals[6], vals[7]);
    }
}

// ---------------------------------------------------------------------------
// Kernel 3: per-(b,d) FFT convolution, in place on g_XT rows.
// grid = 3072; d = blk>>2, b = blk&3 so 4 adjacent CTAs share one VS row (L2).
// ---------------------------------------------------------------------------
__global__ void __launch_bounds__(512, 1)
conv_kernel() {
    extern __shared__ float2 fb[];
    float2* A  = fb;
    float2* Bu = fb + FFT_BUF;

    const int tid = threadIdx.x;
    const int d   = blockIdx.x >> 2;
    const int b   = blockIdx.x & 3;

    float2* row = (float2*)(g_XT + (((size_t)(b * DIM + d)) << 13));

    #pragma unroll 1
    for (int it = 0; it < 16; it++) {
        int i = tid + it * 512;
        A[SMX(i)] = (i < HALF) ? row[i] : make_float2(0.0f, 0.0f);
    }
    __syncthreads();

    fft8192<-1>(A, Bu, tid);

    const float2* vs = g_VS + ((size_t)d << 13);
    #pragma unroll 1
    for (int it = 0; it < 16; it++) {
        int i = tid + it * 512;
        Bu[SMX(i)] = cmul(Bu[SMX(i)], vs[i]);
    }
    __syncthreads();

    fft8192<1>(Bu, A, tid);

    #pragma unroll 1
    for (int it = 0; it < 8; it++) {
        int i = tid + it * 512;            // 0..4095
        row[i] = A[SMX(i)];                // (Re,Im) = (out[2m], out[2m+1])
    }
}

// ---------------------------------------------------------------------------
// Kernel 4: transpose g_XT (B,D,L) -> out (B,L,D)
// ---------------------------------------------------------------------------
__global__ void __launch_bounds__(256, 4)
transpose_kernel(float* __restrict__ out) {
    __shared__ float t[32][33];
    const int b  = blockIdx.z;
    const int l0 = blockIdx.x * 32;
    const int d0 = blockIdx.y * 32;
    const int tx = threadIdx.x, ty = threadIdx.y;   // 32 x 8

    const float* src = g_XT + (size_t)b * DIM * SEQ;
    #pragma unroll
    for (int i = 0; i < 4; i++)
        t[ty + i * 8][tx] = src[(size_t)(d0 + ty + i * 8) * SEQ + l0 + tx];
    __syncthreads();
    float* dst = out + (size_t)b * SEQ * DIM;
    #pragma unroll
    for (int i = 0; i < 4; i++)
        dst[(size_t)(l0 + ty + i * 8) * DIM + d0 + tx] = t[tx][ty + i * 8];
}

// ---------------------------------------------------------------------------
// launch
// ---------------------------------------------------------------------------
extern "C" void kernel_launch(void* const* d_in, const int* in_sizes, int n_in,
                              void* d_out, int out_size) {
    const float* x   = (const float*)d_in[0];
    const float* phi = (const float*)d_in[1];
    const float* Mi  = (const float*)d_in[2];
    const float* Mf  = (const float*)d_in[3];
    float* out = (float*)d_out;

    cudaFuncSetAttribute(filter_kernel, cudaFuncAttributeMaxDynamicSharedMemorySize, FFT_SMEM_BYTES);
    cudaFuncSetAttribute(conv_kernel,   cudaFuncAttributeMaxDynamicSharedMemorySize, FFT_SMEM_BYTES);

    filter_kernel<<<DIM, 512, FFT_SMEM_BYTES>>>(phi, Mf);
    gemm_kernel<<<dim3(DIM / 128, (BATCH * SEQ) / 128), 256>>>(x, Mi);
    conv_kernel<<<BATCH * DIM, 512, FFT_SMEM_BYTES>>>();
    transpose_kernel<<<dim3(SEQ / 32, DIM / 32, BATCH), dim3(32, 8)>>>(out);
}

// round 4
// speedup vs baseline: 1.1776x; 1.1776x over previous
#include <cuda_runtime.h>
#include <cuda_bf16.h>

// ---------------------------------------------------------------------------
// Problem constants: B=4, L=8192, D=768, K=24, NFFT=16384.
// Math: out[t] = 2 * sum_{j even, j<=t} v[j] * u[t-j]
//   => two length-4096 causal convs with v_e[i]=v[2i], fused into ONE complex
//      FFT of size 8192 via z[k] = u[2k] + i*u[2k+1].
// ---------------------------------------------------------------------------

#define BATCH 4
#define SEQ   8192
#define DIM   768
#define NK    24
#define NC    8192            // complex FFT length
#define HALF  4096

// padded/skewed shared-memory indexing for the FFT (kills stride-8 conflicts)
#define SMX(i) ((i) + ((i) >> 4))
#define FFT_BUF 8704          // SMX(8191)=8702 -> 8704 float2 per buffer
#define FFT_SMEM_BYTES (2 * FFT_BUF * (int)sizeof(float2))   // 139264

// Scratch (device globals: no allocation allowed anywhere)
__device__ float  g_XT[(size_t)BATCH * DIM * SEQ];   // (B, D, L) fp32, ~100MB, in place
__device__ float2 g_VS[(size_t)DIM * NC];            // filter spectra, ~50MB

// ---------------------------------------------------------------------------
// complex helpers
// ---------------------------------------------------------------------------
__device__ __forceinline__ float2 cmul(float2 a, float2 b) {
    return make_float2(a.x * b.x - a.y * b.y, a.x * b.y + a.y * b.x);
}

template<int DIR>   // DIR = -1 forward, +1 inverse (unnormalized)
__device__ __forceinline__ void dft4(float2& a, float2& b, float2& c, float2& d) {
    float2 t0 = make_float2(a.x + c.x, a.y + c.y);
    float2 t1 = make_float2(a.x - c.x, a.y - c.y);
    float2 t2 = make_float2(b.x + d.x, b.y + d.y);
    float2 t3 = make_float2(b.x - d.x, b.y - d.y);
    a = make_float2(t0.x + t2.x, t0.y + t2.y);
    c = make_float2(t0.x - t2.x, t0.y - t2.y);
    if (DIR == -1) {
        b = make_float2(t1.x + t3.y, t1.y - t3.x);   // t1 - i t3
        d = make_float2(t1.x - t3.y, t1.y + t3.x);   // t1 + i t3
    } else {
        b = make_float2(t1.x - t3.y, t1.y + t3.x);
        d = make_float2(t1.x + t3.y, t1.y - t3.x);
    }
}

template<int DIR>
__device__ __forceinline__ void dft8(float2 v[8]) {
    const float S = 0.7071067811865476f;
    float2 e0 = v[0], e1 = v[2], e2 = v[4], e3 = v[6];
    float2 o0 = v[1], o1 = v[3], o2 = v[5], o3 = v[7];
    dft4<DIR>(e0, e1, e2, e3);
    dft4<DIR>(o0, o1, o2, o3);
    o1 = cmul(o1, make_float2(S, (float)DIR * S));
    o2 = (DIR == -1) ? make_float2(o2.y, -o2.x) : make_float2(-o2.y, o2.x);
    o3 = cmul(o3, make_float2(-S, (float)DIR * S));
    v[0] = make_float2(e0.x + o0.x, e0.y + o0.y); v[4] = make_float2(e0.x - o0.x, e0.y - o0.y);
    v[1] = make_float2(e1.x + o1.x, e1.y + o1.y); v[5] = make_float2(e1.x - o1.x, e1.y - o1.y);
    v[2] = make_float2(e2.x + o2.x, e2.y + o2.y); v[6] = make_float2(e2.x - o2.x, e2.y - o2.y);
    v[3] = make_float2(e3.x + o3.x, e3.y + o3.y); v[7] = make_float2(e3.x - o3.x, e3.y - o3.y);
}

// Stockham autosort FFT, N=8192 = 8^4 * 2, 512 threads, ping-pong buffers.
template<int DIR>
__device__ __forceinline__ void fft8192(float2* src, float2* dst, int tid) {
    float2* s = src;
    float2* d = dst;
    int Ns = 1;
    #pragma unroll
    for (int st = 0; st < 4; st++) {
        const float angc = (float)DIR * 6.283185307179586f / (8.0f * (float)Ns);
        #pragma unroll
        for (int it = 0; it < 2; it++) {
            int j  = tid + it * 512;            // 0..1023
            int jm = j & (Ns - 1);
            float ang = angc * (float)jm;
            float c, sn;
            __sincosf(ang, &sn, &c);
            float2 w1 = make_float2(c, sn);
            float2 v[8];
            v[0] = s[SMX(j)];
            float2 wr = w1;
            #pragma unroll
            for (int r = 1; r < 8; r++) {
                v[r] = cmul(s[SMX(j + r * 1024)], wr);
                wr = cmul(wr, w1);
            }
            dft8<DIR>(v);
            int base = ((j & ~(Ns - 1)) << 3) + jm;
            #pragma unroll
            for (int r = 0; r < 8; r++) d[SMX(base + r * Ns)] = v[r];
        }
        __syncthreads();
        float2* t = s; s = d; d = t;
        Ns <<= 3;
    }
    const float angc2 = (float)DIR * 6.283185307179586f / 8192.0f;
    #pragma unroll
    for (int it = 0; it < 8; it++) {
        int j = tid + it * 512;                 // 0..4095
        float c, sn;
        __sincosf(angc2 * (float)j, &sn, &c);
        float2 v0 = s[SMX(j)];
        float2 v1 = cmul(s[SMX(j + 4096)], make_float2(c, sn));
        d[SMX(j)]        = make_float2(v0.x + v1.x, v0.y + v1.y);
        d[SMX(j + 4096)] = make_float2(v0.x - v1.x, v0.y - v1.y);
    }
    __syncthreads();
}

// ---------------------------------------------------------------------------
// Kernel 1: filter prep. One CTA per output channel d.
// ---------------------------------------------------------------------------
__global__ void __launch_bounds__(512, 1)
filter_kernel(const float* __restrict__ phi, const float* __restrict__ Mf) {
    extern __shared__ float2 fb[];
    float2* A  = fb;
    float2* Bu = fb + FFT_BUF;
    __shared__ float mf[NK];

    const int tid = threadIdx.x;
    const int d   = blockIdx.x;
    if (tid < NK) mf[tid] = Mf[tid * DIM + d];
    __syncthreads();

    const float sc = 2.0f / 8192.0f;
    #pragma unroll 1
    for (int it = 0; it < 16; it++) {
        int i = tid + it * 512;
        float s = 0.0f;
        if (i < HALF) {
            const float* pr = phi + (size_t)i * (2 * NK);   // row 2i
            #pragma unroll
            for (int k = 0; k < NK; k++) s += pr[k] * mf[k];
        }
        A[SMX(i)] = make_float2(s * sc, 0.0f);
    }
    __syncthreads();

    fft8192<-1>(A, Bu, tid);

    float2* vsd = g_VS + ((size_t)d << 13);
    #pragma unroll 1
    for (int it = 0; it < 16; it++) {
        int i = tid + it * 512;
        vsd[i] = Bu[SMX(i)];
    }
}

// ---------------------------------------------------------------------------
// Kernel 2: GEMM  u = x @ M_inputs  via 3xTF32 mma.sync, transposed epilogue
// into g_XT[b,d,l].
// CTA tile 128(M=l) x 128(N=d), k-chunk 16, 8 warps (warp tile 64x32),
// double-buffered smem holding tf32-split hi/lo planes.
// ---------------------------------------------------------------------------
// cvt.rna.tf32.f32 requires a .b32 destination; the resulting bit pattern is
// a valid fp32 (low mantissa bits zeroed), so lo = x - as_float(hi) is exact.
__device__ __forceinline__ float tf32_hi(float x) {
    unsigned r;
    asm("cvt.rna.tf32.f32 %0, %1;" : "=r"(r) : "f"(x));
    return __uint_as_float(r);
}

__device__ __forceinline__ void mma8(float4& d,
                                     float a0, float a1, float a2, float a3,
                                     float b0, float b1) {
    asm volatile(
        "mma.sync.aligned.m16n8k8.row.col.f32.tf32.tf32.f32 "
        "{%0,%1,%2,%3}, {%4,%5,%6,%7}, {%8,%9}, {%0,%1,%2,%3};"
        : "+f"(d.x), "+f"(d.y), "+f"(d.z), "+f"(d.w)
        : "r"(__float_as_uint(a0)), "r"(__float_as_uint(a1)),
          "r"(__float_as_uint(a2)), "r"(__float_as_uint(a3)),
          "r"(__float_as_uint(b0)), "r"(__float_as_uint(b1)));
}

#define GSZ 2112            // 16 * 132 floats per plane per buffer
#define GEMM_SMEM_BYTES (8 * GSZ * (int)sizeof(float))   // 67584

__global__ void __launch_bounds__(256, 1)
gemm_kernel(const float* __restrict__ X, const float* __restrict__ Mi) {
    extern __shared__ float sm[];
    float* AH = sm;             // [2][16][132]
    float* AL = sm + 2 * GSZ;
    float* BH = sm + 4 * GSZ;
    float* BL = sm + 6 * GSZ;

    const int tid  = threadIdx.x;
    const int wid  = tid >> 5;
    const int lane = tid & 31;
    const int g    = lane >> 2;       // 0..7
    const int tig  = lane & 3;        // 0..3
    const int wm   = wid & 1;         // warp row (64 l-rows each)
    const int wn   = wid >> 1;        // warp col (32 d-cols each)

    const int n0 = blockIdx.x * 128;
    const int l0 = blockIdx.y * 128;

    const float* Ab = X  + (size_t)l0 * DIM;
    const float* Bb = Mi + n0;

    float4 ra[2], rb[2];

    // prologue: load chunk 0 into buffer 0
    #pragma unroll
    for (int u = 0; u < 2; u++) {
        int i = tid + u * 256;
        ra[u] = *(const float4*)(Ab + (size_t)(i >> 2) * DIM + (i & 3) * 4);
        rb[u] = *(const float4*)(Bb + (size_t)(i >> 5) * DIM + (i & 31) * 4);
    }
    #pragma unroll
    for (int u = 0; u < 2; u++) {
        int i = tid + u * 256;
        int m = i >> 2, k4 = i & 3;
        float va[4] = {ra[u].x, ra[u].y, ra[u].z, ra[u].w};
        #pragma unroll
        for (int e = 0; e < 4; e++) {
            float hi = tf32_hi(va[e]);
            AH[(k4 * 4 + e) * 132 + m] = hi;
            AL[(k4 * 4 + e) * 132 + m] = va[e] - hi;
        }
        int kr = i >> 5, nc = (i & 31) * 4;
        float vb[4] = {rb[u].x, rb[u].y, rb[u].z, rb[u].w};
        float4 bh, bl;
        bh.x = tf32_hi(vb[0]); bl.x = vb[0] - bh.x;
        bh.y = tf32_hi(vb[1]); bl.y = vb[1] - bh.y;
        bh.z = tf32_hi(vb[2]); bl.z = vb[2] - bh.z;
        bh.w = tf32_hi(vb[3]); bl.w = vb[3] - bh.w;
        *(float4*)&BH[kr * 132 + nc] = bh;
        *(float4*)&BL[kr * 132 + nc] = bl;
    }
    __syncthreads();

    float4 acc[4][4];
    #pragma unroll
    for (int mt = 0; mt < 4; mt++)
        #pragma unroll
        for (int nt = 0; nt < 4; nt++)
            acc[mt][nt] = make_float4(0.f, 0.f, 0.f, 0.f);

    #pragma unroll 1
    for (int kc = 0; kc < 48; kc++) {
        if (kc < 47) {
            #pragma unroll
            for (int u = 0; u < 2; u++) {
                int i = tid + u * 256;
                ra[u] = *(const float4*)(Ab + (size_t)(i >> 2) * DIM + (kc + 1) * 16 + (i & 3) * 4);
                rb[u] = *(const float4*)(Bb + (size_t)((kc + 1) * 16 + (i >> 5)) * DIM + (i & 31) * 4);
            }
        }
        const int bf = (kc & 1) * GSZ;
        const int m0 = wm * 64;
        const int nb0 = wn * 32;

        #pragma unroll
        for (int ks = 0; ks < 2; ks++) {
            const int k8 = ks * 8;
            const float* ah = AH + bf + (k8 + tig) * 132;
            const float* al = AL + bf + (k8 + tig) * 132;
            const float* bhp = BH + bf + (k8 + tig) * 132;
            const float* blp = BL + bf + (k8 + tig) * 132;

            float fah[4][4], fal[4][4];
            #pragma unroll
            for (int mt = 0; mt < 4; mt++) {
                int mm = m0 + mt * 16 + g;
                fah[mt][0] = ah[mm];            fah[mt][1] = ah[mm + 8];
                fah[mt][2] = ah[4 * 132 + mm];  fah[mt][3] = ah[4 * 132 + mm + 8];
                fal[mt][0] = al[mm];            fal[mt][1] = al[mm + 8];
                fal[mt][2] = al[4 * 132 + mm];  fal[mt][3] = al[4 * 132 + mm + 8];
            }
            float fbh[4][2], fbl[4][2];
            #pragma unroll
            for (int nt = 0; nt < 4; nt++) {
                int nn = nb0 + nt * 8 + g;
                fbh[nt][0] = bhp[nn]; fbh[nt][1] = bhp[4 * 132 + nn];
                fbl[nt][0] = blp[nn]; fbl[nt][1] = blp[4 * 132 + nn];
            }
            // pass 1: hi*hi
            #pragma unroll
            for (int mt = 0; mt < 4; mt++)
                #pragma unroll
                for (int nt = 0; nt < 4; nt++)
                    mma8(acc[mt][nt], fah[mt][0], fah[mt][1], fah[mt][2], fah[mt][3],
                         fbh[nt][0], fbh[nt][1]);
            // pass 2: hi*lo
            #pragma unroll
            for (int mt = 0; mt < 4; mt++)
                #pragma unroll
                for (int nt = 0; nt < 4; nt++)
                    mma8(acc[mt][nt], fah[mt][0], fah[mt][1], fah[mt][2], fah[mt][3],
                         fbl[nt][0], fbl[nt][1]);
            // pass 3: lo*hi
            #pragma unroll
            for (int mt = 0; mt < 4; mt++)
                #pragma unroll
                for (int nt = 0; nt < 4; nt++)
                    mma8(acc[mt][nt], fal[mt][0], fal[mt][1], fal[mt][2], fal[mt][3],
                         fbh[nt][0], fbh[nt][1]);
        }

        if (kc < 47) {
            const int nbuf = ((kc + 1) & 1) * GSZ;
            #pragma unroll
            for (int u = 0; u < 2; u++) {
                int i = tid + u * 256;
                int m = i >> 2, k4 = i & 3;
                float va[4] = {ra[u].x, ra[u].y, ra[u].z, ra[u].w};
                #pragma unroll
                for (int e = 0; e < 4; e++) {
                    float hi = tf32_hi(va[e]);
                    AH[nbuf + (k4 * 4 + e) * 132 + m] = hi;
                    AL[nbuf + (k4 * 4 + e) * 132 + m] = va[e] - hi;
                }
                int kr = i >> 5, nc = (i & 31) * 4;
                float vb[4] = {rb[u].x, rb[u].y, rb[u].z, rb[u].w};
                float4 bh, bl;
                bh.x = tf32_hi(vb[0]); bl.x = vb[0] - bh.x;
                bh.y = tf32_hi(vb[1]); bl.y = vb[1] - bh.y;
                bh.z = tf32_hi(vb[2]); bl.z = vb[2] - bh.z;
                bh.w = tf32_hi(vb[3]); bl.w = vb[3] - bh.w;
                *(float4*)&BH[nbuf + kr * 132 + nc] = bh;
                *(float4*)&BL[nbuf + kr * 132 + nc] = bl;
            }
            __syncthreads();
        }
    }

    // epilogue: write transposed -> g_XT[b, d, l]
    const int b    = l0 >> 13;
    const int lloc = l0 & (SEQ - 1);
    #pragma unroll
    for (int mt = 0; mt < 4; mt++) {
        const int lbase = lloc + wm * 64 + mt * 16 + g;
        #pragma unroll
        for (int nt = 0; nt < 4; nt++) {
            const int d0 = n0 + wn * 32 + nt * 8 + 2 * tig;
            float4 c = acc[mt][nt];
            float* pa = g_XT + (((size_t)(b * DIM + d0)) << 13) + lbase;
            float* pb = g_XT + (((size_t)(b * DIM + d0 + 1)) << 13) + lbase;
            pa[0] = c.x; pb[0] = c.y;
            pa[8] = c.z; pb[8] = c.w;
        }
    }
}

// ---------------------------------------------------------------------------
// Kernel 3: per-(b,d) FFT convolution, in place on g_XT rows.
// ---------------------------------------------------------------------------
__global__ void __launch_bounds__(512, 1)
conv_kernel() {
    extern __shared__ float2 fb[];
    float2* A  = fb;
    float2* Bu = fb + FFT_BUF;

    const int tid = threadIdx.x;
    const int d   = blockIdx.x >> 2;
    const int b   = blockIdx.x & 3;

    float2* row = (float2*)(g_XT + (((size_t)(b * DIM + d)) << 13));

    #pragma unroll 1
    for (int it = 0; it < 16; it++) {
        int i = tid + it * 512;
        A[SMX(i)] = (i < HALF) ? row[i] : make_float2(0.0f, 0.0f);
    }
    __syncthreads();

    fft8192<-1>(A, Bu, tid);

    const float2* vs = g_VS + ((size_t)d << 13);
    #pragma unroll 1
    for (int it = 0; it < 16; it++) {
        int i = tid + it * 512;
        Bu[SMX(i)] = cmul(Bu[SMX(i)], vs[i]);
    }
    __syncthreads();

    fft8192<1>(Bu, A, tid);

    #pragma unroll 1
    for (int it = 0; it < 8; it++) {
        int i = tid + it * 512;            // 0..4095
        row[i] = A[SMX(i)];                // (Re,Im) = (out[2m], out[2m+1])
    }
}

// ---------------------------------------------------------------------------
// Kernel 4: transpose g_XT (B,D,L) -> out (B,L,D)
// ---------------------------------------------------------------------------
__global__ void __launch_bounds__(256, 4)
transpose_kernel(float* __restrict__ out) {
    __shared__ float t[32][33];
    const int b  = blockIdx.z;
    const int l0 = blockIdx.x * 32;
    const int d0 = blockIdx.y * 32;
    const int tx = threadIdx.x, ty = threadIdx.y;   // 32 x 8

    const float* src = g_XT + (size_t)b * DIM * SEQ;
    #pragma unroll
    for (int i = 0; i < 4; i++)
        t[ty + i * 8][tx] = src[(size_t)(d0 + ty + i * 8) * SEQ + l0 + tx];
    __syncthreads();
    float* dst = out + (size_t)b * SEQ * DIM;
    #pragma unroll
    for (int i = 0; i < 4; i++)
        dst[(size_t)(l0 + ty + i * 8) * DIM + d0 + tx] = t[tx][ty + i * 8];
}

// ---------------------------------------------------------------------------
// launch
// ---------------------------------------------------------------------------
extern "C" void kernel_launch(void* const* d_in, const int* in_sizes, int n_in,
                              void* d_out, int out_size) {
    const float* x   = (const float*)d_in[0];
    const float* phi = (const float*)d_in[1];
    const float* Mi  = (const float*)d_in[2];
    const float* Mf  = (const float*)d_in[3];
    float* out = (float*)d_out;

    cudaFuncSetAttribute(filter_kernel, cudaFuncAttributeMaxDynamicSharedMemorySize, FFT_SMEM_BYTES);
    cudaFuncSetAttribute(conv_kernel,   cudaFuncAttributeMaxDynamicSharedMemorySize, FFT_SMEM_BYTES);
    cudaFuncSetAttribute(gemm_kernel,   cudaFuncAttributeMaxDynamicSharedMemorySize, GEMM_SMEM_BYTES);

    filter_kernel<<<DIM, 512, FFT_SMEM_BYTES>>>(phi, Mf);
    gemm_kernel<<<dim3(DIM / 128, (BATCH * SEQ) / 128), 256, GEMM_SMEM_BYTES>>>(x, Mi);
    conv_kernel<<<BATCH * DIM, 512, FFT_SMEM_BYTES>>>();
    transpose_kernel<<<dim3(SEQ / 32, DIM / 32, BATCH), dim3(32, 8)>>>(out);
}

// round 8
// speedup vs baseline: 1.4429x; 1.2253x over previous
#include <cuda_runtime.h>
#include <cuda_bf16.h>
#include <cstdint>

// ---------------------------------------------------------------------------
// Problem constants: B=4, L=8192, D=768, K=24, NFFT=16384.
// Math: out[t] = 2 * sum_{j even, j<=t} v[j] * u[t-j]
//   => two length-4096 causal convs with v_e[i]=v[2i], fused into ONE complex
//      FFT of size 8192 via z[k] = u[2k] + i*u[2k+1].
// ---------------------------------------------------------------------------

#define BATCH 4
#define SEQ   8192
#define DIM   768
#define NK    24
#define NC    8192            // complex FFT length
#define HALF  4096

// padded/skewed shared-memory indexing for the FFT (kills stride-8 conflicts)
#define SMX(i) ((i) + ((i) >> 4))
#define FFT_BUF 8704
#define FFT_SMEM_BYTES (2 * FFT_BUF * (int)sizeof(float2))   // 139264

// Scratch (device globals: no allocation allowed anywhere)
__device__ float  g_XT[(size_t)BATCH * DIM * SEQ];   // (B, D, L) fp32, in place
__device__ float2 g_VS[(size_t)DIM * NC];            // filter spectra

// ---------------------------------------------------------------------------
// complex helpers
// ---------------------------------------------------------------------------
__device__ __forceinline__ float2 cmul(float2 a, float2 b) {
    return make_float2(a.x * b.x - a.y * b.y, a.x * b.y + a.y * b.x);
}

template<int DIR>   // DIR = -1 forward, +1 inverse (unnormalized)
__device__ __forceinline__ void dft4(float2& a, float2& b, float2& c, float2& d) {
    float2 t0 = make_float2(a.x + c.x, a.y + c.y);
    float2 t1 = make_float2(a.x - c.x, a.y - c.y);
    float2 t2 = make_float2(b.x + d.x, b.y + d.y);
    float2 t3 = make_float2(b.x - d.x, b.y - d.y);
    a = make_float2(t0.x + t2.x, t0.y + t2.y);
    c = make_float2(t0.x - t2.x, t0.y - t2.y);
    if (DIR == -1) {
        b = make_float2(t1.x + t3.y, t1.y - t3.x);
        d = make_float2(t1.x - t3.y, t1.y + t3.x);
    } else {
        b = make_float2(t1.x - t3.y, t1.y + t3.x);
        d = make_float2(t1.x + t3.y, t1.y - t3.x);
    }
}

template<int DIR>
__device__ __forceinline__ void dft8(float2 v[8]) {
    const float S = 0.7071067811865476f;
    float2 e0 = v[0], e1 = v[2], e2 = v[4], e3 = v[6];
    float2 o0 = v[1], o1 = v[3], o2 = v[5], o3 = v[7];
    dft4<DIR>(e0, e1, e2, e3);
    dft4<DIR>(o0, o1, o2, o3);
    o1 = cmul(o1, make_float2(S, (float)DIR * S));
    o2 = (DIR == -1) ? make_float2(o2.y, -o2.x) : make_float2(-o2.y, o2.x);
    o3 = cmul(o3, make_float2(-S, (float)DIR * S));
    v[0] = make_float2(e0.x + o0.x, e0.y + o0.y); v[4] = make_float2(e0.x - o0.x, e0.y - o0.y);
    v[1] = make_float2(e1.x + o1.x, e1.y + o1.y); v[5] = make_float2(e1.x - o1.x, e1.y - o1.y);
    v[2] = make_float2(e2.x + o2.x, e2.y + o2.y); v[6] = make_float2(e2.x - o2.x, e2.y - o2.y);
    v[3] = make_float2(e3.x + o3.x, e3.y + o3.y); v[7] = make_float2(e3.x - o3.x, e3.y - o3.y);
}

// Stockham autosort FFT, N=8192 = 8^4 * 2, 512 threads, ping-pong buffers.
template<int DIR>
__device__ __forceinline__ void fft8192(float2* src, float2* dst, int tid) {
    float2* s = src;
    float2* d = dst;
    int Ns = 1;
    #pragma unroll
    for (int st = 0; st < 4; st++) {
        const float angc = (float)DIR * 6.283185307179586f / (8.0f * (float)Ns);
        #pragma unroll
        for (int it = 0; it < 2; it++) {
            int j  = tid + it * 512;
            int jm = j & (Ns - 1);
            float ang = angc * (float)jm;
            float c, sn;
            __sincosf(ang, &sn, &c);
            float2 w1 = make_float2(c, sn);
            float2 v[8];
            v[0] = s[SMX(j)];
            float2 wr = w1;
            #pragma unroll
            for (int r = 1; r < 8; r++) {
                v[r] = cmul(s[SMX(j + r * 1024)], wr);
                wr = cmul(wr, w1);
            }
            dft8<DIR>(v);
            int base = ((j & ~(Ns - 1)) << 3) + jm;
            #pragma unroll
            for (int r = 0; r < 8; r++) d[SMX(base + r * Ns)] = v[r];
        }
        __syncthreads();
        float2* t = s; s = d; d = t;
        Ns <<= 3;
    }
    const float angc2 = (float)DIR * 6.283185307179586f / 8192.0f;
    #pragma unroll
    for (int it = 0; it < 8; it++) {
        int j = tid + it * 512;
        float c, sn;
        __sincosf(angc2 * (float)j, &sn, &c);
        float2 v0 = s[SMX(j)];
        float2 v1 = cmul(s[SMX(j + 4096)], make_float2(c, sn));
        d[SMX(j)]        = make_float2(v0.x + v1.x, v0.y + v1.y);
        d[SMX(j + 4096)] = make_float2(v0.x - v1.x, v0.y - v1.y);
    }
    __syncthreads();
}

// ---------------------------------------------------------------------------
// Kernel 1: filter prep. One CTA per output channel d.
// ---------------------------------------------------------------------------
__global__ void __launch_bounds__(512, 1)
filter_kernel(const float* __restrict__ phi, const float* __restrict__ Mf) {
    extern __shared__ float2 fb[];
    float2* A  = fb;
    float2* Bu = fb + FFT_BUF;
    __shared__ float mf[NK];

    const int tid = threadIdx.x;
    const int d   = blockIdx.x;
    if (tid < NK) mf[tid] = Mf[tid * DIM + d];
    __syncthreads();

    const float sc = 2.0f / 8192.0f;
    #pragma unroll 1
    for (int it = 0; it < 16; it++) {
        int i = tid + it * 512;
        float s = 0.0f;
        if (i < HALF) {
            const float* pr = phi + (size_t)i * (2 * NK);
            #pragma unroll
            for (int k = 0; k < NK; k++) s += pr[k] * mf[k];
        }
        A[SMX(i)] = make_float2(s * sc, 0.0f);
    }
    __syncthreads();

    fft8192<-1>(A, Bu, tid);

    float2* vsd = g_VS + ((size_t)d << 13);
    #pragma unroll 1
    for (int it = 0; it < 16; it++) {
        int i = tid + it * 512;
        vsd[i] = Bu[SMX(i)];
    }
}

// ---------------------------------------------------------------------------
// Kernel 2: GEMM  u = x @ M_inputs via bf16 mma.sync m16n8k16, 3-pass split
// (hi*hi + hi*lo + lo*hi). CTA tile 128(M=l) x 128(N=d), K chunks of 32,
// double-buffered smem of k-pair-packed u32 planes W[k2][row], pitch 134.
// Transposed epilogue into g_XT[b,d,l].
// ---------------------------------------------------------------------------
__device__ __forceinline__ uint32_t pkbf(float lo, float hi) {
    uint32_t r;
    asm("cvt.rn.bf16x2.f32 %0, %1, %2;" : "=r"(r) : "f"(hi), "f"(lo));
    return r;
}
__device__ __forceinline__ float bfhi(float x) {
    return __bfloat162float(__float2bfloat16_rn(x));
}
__device__ __forceinline__ void mma16(float4& d,
                                      uint32_t a0, uint32_t a1, uint32_t a2, uint32_t a3,
                                      uint32_t b0, uint32_t b1) {
    asm volatile(
        "mma.sync.aligned.m16n8k16.row.col.f32.bf16.bf16.f32 "
        "{%0,%1,%2,%3}, {%4,%5,%6,%7}, {%8,%9}, {%0,%1,%2,%3};"
        : "+f"(d.x), "+f"(d.y), "+f"(d.z), "+f"(d.w)
        : "r"(a0), "r"(a1), "r"(a2), "r"(a3), "r"(b0), "r"(b1));
}

#define GPITCH 134
#define GPLANE (16 * GPITCH)            // u32 words per plane (k2 0..15)
#define GBUFW  (4 * GPLANE)             // AH, AL, BH, BL
#define GEMM_DYN_BYTES (2 * GBUFW * (int)sizeof(uint32_t))   // 68608

__global__ void __launch_bounds__(256, 1)
gemm_kernel(const float* __restrict__ X, const float* __restrict__ Mi) {
    extern __shared__ uint32_t sm[];

    const int tid  = threadIdx.x;
    const int wid  = tid >> 5;
    const int lane = tid & 31;
    const int g    = lane >> 2;       // 0..7
    const int tig  = lane & 3;        // 0..3
    const int wm   = wid & 1;         // warp m-half (64 rows)
    const int wn   = wid >> 1;        // warp n-quarter (32 cols)
    const int m0   = wm * 64;
    const int nw0  = wn * 32;

    const int n0 = blockIdx.x * 128;
    const int l0 = blockIdx.y * 128;

    const int arow = tid >> 1;        // 0..127 (A m-row / B n-col)
    const int akh  = tid & 1;         // k half (16 each)

    const float* ap = X  + (size_t)(l0 + arow) * DIM + akh * 16;
    const float* bp = Mi + (size_t)(akh * 16) * DIM + n0 + arow;

    float fa[16], fbv[16];

    // ---- load chunk 0 ----
    {
        #pragma unroll
        for (int q = 0; q < 4; q++) {
            float4 v = *(const float4*)(ap + q * 4);
            fa[q*4+0] = v.x; fa[q*4+1] = v.y; fa[q*4+2] = v.z; fa[q*4+3] = v.w;
        }
        #pragma unroll
        for (int j = 0; j < 16; j++) fbv[j] = bp[(size_t)j * DIM];
    }
    // store chunk 0 into buffer 0
    {
        uint32_t* W = sm;
        #pragma unroll
        for (int j = 0; j < 8; j++) {
            int idx = (akh * 8 + j) * GPITCH + arow;
            float x0 = fa[2*j], x1 = fa[2*j+1];
            float h0 = bfhi(x0), h1 = bfhi(x1);
            W[idx]          = pkbf(h0, h1);
            W[GPLANE + idx] = pkbf(x0 - h0, x1 - h1);
            float y0 = fbv[2*j], y1 = fbv[2*j+1];
            float e0 = bfhi(y0), e1 = bfhi(y1);
            W[2*GPLANE + idx] = pkbf(e0, e1);
            W[3*GPLANE + idx] = pkbf(y0 - e0, y1 - e1);
        }
    }
    __syncthreads();

    float4 acc[4][4];
    #pragma unroll
    for (int mt = 0; mt < 4; mt++)
        #pragma unroll
        for (int nt = 0; nt < 4; nt++)
            acc[mt][nt] = make_float4(0.f, 0.f, 0.f, 0.f);

    #pragma unroll 1
    for (int c = 0; c < 24; c++) {
        // prefetch chunk c+1
        if (c < 23) {
            const int k0 = (c + 1) * 32;
            #pragma unroll
            for (int q = 0; q < 4; q++) {
                float4 v = *(const float4*)(ap + k0 + q * 4);
                fa[q*4+0] = v.x; fa[q*4+1] = v.y; fa[q*4+2] = v.z; fa[q*4+3] = v.w;
            }
            #pragma unroll
            for (int j = 0; j < 16; j++) fbv[j] = bp[(size_t)(k0 + j) * DIM];
        }

        // ---- compute on buffer c&1 ----
        const uint32_t* W   = sm + (c & 1) * GBUFW;
        const uint32_t* WAH = W;
        const uint32_t* WAL = W + GPLANE;
        const uint32_t* WBH = W + 2 * GPLANE;
        const uint32_t* WBL = W + 3 * GPLANE;

        #pragma unroll
        for (int ks = 0; ks < 2; ks++) {
            const int kb = ks * 8;
            uint32_t fah[4][4], fbh[4][2];
            {
                const uint32_t* pA = WAH + (kb + tig) * GPITCH;
                #pragma unroll
                for (int mt = 0; mt < 4; mt++) {
                    int mm = m0 + mt * 16 + g;
                    fah[mt][0] = pA[mm];
                    fah[mt][1] = pA[mm + 8];
                    fah[mt][2] = pA[4 * GPITCH + mm];
                    fah[mt][3] = pA[4 * GPITCH + mm + 8];
                }
                const uint32_t* pB = WBH + (kb + tig) * GPITCH;
                #pragma unroll
                for (int nt = 0; nt < 4; nt++) {
                    int nn = nw0 + nt * 8 + g;
                    fbh[nt][0] = pB[nn];
                    fbh[nt][1] = pB[4 * GPITCH + nn];
                }
            }
            // pass 1: hi*hi
            #pragma unroll
            for (int mt = 0; mt < 4; mt++)
                #pragma unroll
                for (int nt = 0; nt < 4; nt++)
                    mma16(acc[mt][nt], fah[mt][0], fah[mt][1], fah[mt][2], fah[mt][3],
                          fbh[nt][0], fbh[nt][1]);
            // pass 2: hi*lo
            {
                uint32_t fbl[4][2];
                const uint32_t* pB = WBL + (kb + tig) * GPITCH;
                #pragma unroll
                for (int nt = 0; nt < 4; nt++) {
                    int nn = nw0 + nt * 8 + g;
                    fbl[nt][0] = pB[nn];
                    fbl[nt][1] = pB[4 * GPITCH + nn];
                }
                #pragma unroll
                for (int mt = 0; mt < 4; mt++)
                    #pragma unroll
                    for (int nt = 0; nt < 4; nt++)
                        mma16(acc[mt][nt], fah[mt][0], fah[mt][1], fah[mt][2], fah[mt][3],
                              fbl[nt][0], fbl[nt][1]);
            }
            // pass 3: lo*hi
            {
                uint32_t fal[4][4];
                const uint32_t* pA = WAL + (kb + tig) * GPITCH;
                #pragma unroll
                for (int mt = 0; mt < 4; mt++) {
                    int mm = m0 + mt * 16 + g;
                    fal[mt][0] = pA[mm];
                    fal[mt][1] = pA[mm + 8];
                    fal[mt][2] = pA[4 * GPITCH + mm];
                    fal[mt][3] = pA[4 * GPITCH + mm + 8];
                }
                #pragma unroll
                for (int mt = 0; mt < 4; mt++)
                    #pragma unroll
                    for (int nt = 0; nt < 4; nt++)
                        mma16(acc[mt][nt], fal[mt][0], fal[mt][1], fal[mt][2], fal[mt][3],
                              fbh[nt][0], fbh[nt][1]);
            }
        }

        // ---- store chunk c+1 into buffer (c+1)&1 ----
        if (c < 23) {
            __syncthreads();   // everyone done reading buffer (c+1)&1 (= chunk c-1)
            uint32_t* Wn = sm + ((c + 1) & 1) * GBUFW;
            #pragma unroll
            for (int j = 0; j < 8; j++) {
                int idx = (akh * 8 + j) * GPITCH + arow;
                float x0 = fa[2*j], x1 = fa[2*j+1];
                float h0 = bfhi(x0), h1 = bfhi(x1);
                Wn[idx]          = pkbf(h0, h1);
                Wn[GPLANE + idx] = pkbf(x0 - h0, x1 - h1);
                float y0 = fbv[2*j], y1 = fbv[2*j+1];
                float e0 = bfhi(y0), e1 = bfhi(y1);
                Wn[2*GPLANE + idx] = pkbf(e0, e1);
                Wn[3*GPLANE + idx] = pkbf(y0 - e0, y1 - e1);
            }
            __syncthreads();
        }
    }

    // ---- epilogue: write transposed -> g_XT[b, d, l] ----
    const int b    = l0 >> 13;
    const int lloc = l0 & (SEQ - 1);
    #pragma unroll
    for (int mt = 0; mt < 4; mt++) {
        const int lbase = lloc + m0 + mt * 16 + g;
        #pragma unroll
        for (int nt = 0; nt < 4; nt++) {
            const int d0 = n0 + nw0 + nt * 8 + 2 * tig;
            float4 cc = acc[mt][nt];
            float* pa = g_XT + (((size_t)(b * DIM + d0)) << 13) + lbase;
            float* pb = g_XT + (((size_t)(b * DIM + d0 + 1)) << 13) + lbase;
            pa[0] = cc.x; pb[0] = cc.y;
            pa[8] = cc.z; pb[8] = cc.w;
        }
    }
}

// ---------------------------------------------------------------------------
// Kernel 3: per-(b,d) FFT convolution, in place on g_XT rows.
// ---------------------------------------------------------------------------
__global__ void __launch_bounds__(512, 1)
conv_kernel() {
    extern __shared__ float2 fb[];
    float2* A  = fb;
    float2* Bu = fb + FFT_BUF;

    const int tid = threadIdx.x;
    const int d   = blockIdx.x >> 2;
    const int b   = blockIdx.x & 3;

    float2* row = (float2*)(g_XT + (((size_t)(b * DIM + d)) << 13));

    #pragma unroll 1
    for (int it = 0; it < 16; it++) {
        int i = tid + it * 512;
        A[SMX(i)] = (i < HALF) ? row[i] : make_float2(0.0f, 0.0f);
    }
    __syncthreads();

    fft8192<-1>(A, Bu, tid);

    const float2* vs = g_VS + ((size_t)d << 13);
    #pragma unroll 1
    for (int it = 0; it < 16; it++) {
        int i = tid + it * 512;
        Bu[SMX(i)] = cmul(Bu[SMX(i)], vs[i]);
    }
    __syncthreads();

    fft8192<1>(Bu, A, tid);

    #pragma unroll 1
    for (int it = 0; it < 8; it++) {
        int i = tid + it * 512;
        row[i] = A[SMX(i)];                // (Re,Im) = (out[2m], out[2m+1])
    }
}

// ---------------------------------------------------------------------------
// Kernel 4: transpose g_XT (B,D,L) -> out (B,L,D)
// ---------------------------------------------------------------------------
__global__ void __launch_bounds__(256, 4)
transpose_kernel(float* __restrict__ out) {
    __shared__ float t[32][33];
    const int b  = blockIdx.z;
    const int l0 = blockIdx.x * 32;
    const int d0 = blockIdx.y * 32;
    const int tx = threadIdx.x, ty = threadIdx.y;   // 32 x 8

    const float* src = g_XT + (size_t)b * DIM * SEQ;
    #pragma unroll
    for (int i = 0; i < 4; i++)
        t[ty + i * 8][tx] = src[(size_t)(d0 + ty + i * 8) * SEQ + l0 + tx];
    __syncthreads();
    float* dst = out + (size_t)b * SEQ * DIM;
    #pragma unroll
    for (int i = 0; i < 4; i++)
        dst[(size_t)(l0 + ty + i * 8) * DIM + d0 + tx] = t[tx][ty + i * 8];
}

// ---------------------------------------------------------------------------
// launch
// ---------------------------------------------------------------------------
extern "C" void kernel_launch(void* const* d_in, const int* in_sizes, int n_in,
                              void* d_out, int out_size) {
    const float* x   = (const float*)d_in[0];
    const float* phi = (const float*)d_in[1];
    const float* Mi  = (const float*)d_in[2];
    const float* Mf  = (const float*)d_in[3];
    float* out = (float*)d_out;

    cudaFuncSetAttribute(filter_kernel, cudaFuncAttributeMaxDynamicSharedMemorySize, FFT_SMEM_BYTES);
    cudaFuncSetAttribute(conv_kernel,   cudaFuncAttributeMaxDynamicSharedMemorySize, FFT_SMEM_BYTES);
    cudaFuncSetAttribute(gemm_kernel,   cudaFuncAttributeMaxDynamicSharedMemorySize, GEMM_DYN_BYTES);

    filter_kernel<<<DIM, 512, FFT_SMEM_BYTES>>>(phi, Mf);
    gemm_kernel<<<dim3(DIM / 128, (BATCH * SEQ) / 128), 256, GEMM_DYN_BYTES>>>(x, Mi);
    conv_kernel<<<BATCH * DIM, 512, FFT_SMEM_BYTES>>>();
    transpose_kernel<<<dim3(SEQ / 32, DIM / 32, BATCH), dim3(32, 8)>>>(out);
}

// round 10
// speedup vs baseline: 1.4756x; 1.0226x over previous
#include <cuda_runtime.h>
#include <cuda_bf16.h>
#include <cstdint>

// ---------------------------------------------------------------------------
// Problem constants: B=4, L=8192, D=768, K=24, NFFT=16384.
// Math: out[t] = 2 * sum_{j even, j<=t} v[j] * u[t-j]
//   => two length-4096 causal convs with v_e[i]=v[2i], fused into ONE complex
//      FFT of size 8192 via z[k] = u[2k] + i*u[2k+1].
// GEMM u = x @ M_inputs runs as 3-pass bf16 split (AH*BH + AH*BL + AL*BH)
// with hi/lo planes precomputed once in global memory.
// ---------------------------------------------------------------------------

#define BATCH 4
#define SEQ   8192
#define DIM   768
#define NK    24
#define NC    8192
#define HALF  4096

#define SMX(i) ((i) + ((i) >> 4))
#define FFT_BUF 8704
#define FFT_SMEM_BYTES (2 * FFT_BUF * (int)sizeof(float2))   // 139264

// Scratch (device globals: no allocation allowed anywhere)
__device__ float    g_XT[(size_t)BATCH * DIM * SEQ];   // (B, D, L) fp32, in place
__device__ float2   g_VS[(size_t)DIM * NC];            // filter spectra
__device__ uint32_t g_AHw[(size_t)BATCH * SEQ * DIM / 2];  // x hi, bf16 pairs
__device__ uint32_t g_ALw[(size_t)BATCH * SEQ * DIM / 2];  // x lo
__device__ uint32_t g_BHw[(size_t)DIM * DIM / 2];          // Mi^T hi, [n][k] pairs
__device__ uint32_t g_BLw[(size_t)DIM * DIM / 2];          // Mi^T lo

// ---------------------------------------------------------------------------
// complex helpers
// ---------------------------------------------------------------------------
__device__ __forceinline__ float2 cmul(float2 a, float2 b) {
    return make_float2(a.x * b.x - a.y * b.y, a.x * b.y + a.y * b.x);
}

template<int DIR>
__device__ __forceinline__ void dft4(float2& a, float2& b, float2& c, float2& d) {
    float2 t0 = make_float2(a.x + c.x, a.y + c.y);
    float2 t1 = make_float2(a.x - c.x, a.y - c.y);
    float2 t2 = make_float2(b.x + d.x, b.y + d.y);
    float2 t3 = make_float2(b.x - d.x, b.y - d.y);
    a = make_float2(t0.x + t2.x, t0.y + t2.y);
    c = make_float2(t0.x - t2.x, t0.y - t2.y);
    if (DIR == -1) {
        b = make_float2(t1.x + t3.y, t1.y - t3.x);
        d = make_float2(t1.x - t3.y, t1.y + t3.x);
    } else {
        b = make_float2(t1.x - t3.y, t1.y + t3.x);
        d = make_float2(t1.x + t3.y, t1.y - t3.x);
    }
}

template<int DIR>
__device__ __forceinline__ void dft8(float2 v[8]) {
    const float S = 0.7071067811865476f;
    float2 e0 = v[0], e1 = v[2], e2 = v[4], e3 = v[6];
    float2 o0 = v[1], o1 = v[3], o2 = v[5], o3 = v[7];
    dft4<DIR>(e0, e1, e2, e3);
    dft4<DIR>(o0, o1, o2, o3);
    o1 = cmul(o1, make_float2(S, (float)DIR * S));
    o2 = (DIR == -1) ? make_float2(o2.y, -o2.x) : make_float2(-o2.y, o2.x);
    o3 = cmul(o3, make_float2(-S, (float)DIR * S));
    v[0] = make_float2(e0.x + o0.x, e0.y + o0.y); v[4] = make_float2(e0.x - o0.x, e0.y - o0.y);
    v[1] = make_float2(e1.x + o1.x, e1.y + o1.y); v[5] = make_float2(e1.x - o1.x, e1.y - o1.y);
    v[2] = make_float2(e2.x + o2.x, e2.y + o2.y); v[6] = make_float2(e2.x - o2.x, e2.y - o2.y);
    v[3] = make_float2(e3.x + o3.x, e3.y + o3.y); v[7] = make_float2(e3.x - o3.x, e3.y - o3.y);
}

template<int DIR>
__device__ __forceinline__ void fft8192(float2* src, float2* dst, int tid) {
    float2* s = src;
    float2* d = dst;
    int Ns = 1;
    #pragma unroll
    for (int st = 0; st < 4; st++) {
        const float angc = (float)DIR * 6.283185307179586f / (8.0f * (float)Ns);
        #pragma unroll
        for (int it = 0; it < 2; it++) {
            int j  = tid + it * 512;
            int jm = j & (Ns - 1);
            float ang = angc * (float)jm;
            float c, sn;
            __sincosf(ang, &sn, &c);
            float2 w1 = make_float2(c, sn);
            float2 v[8];
            v[0] = s[SMX(j)];
            float2 wr = w1;
            #pragma unroll
            for (int r = 1; r < 8; r++) {
                v[r] = cmul(s[SMX(j + r * 1024)], wr);
                wr = cmul(wr, w1);
            }
            dft8<DIR>(v);
            int base = ((j & ~(Ns - 1)) << 3) + jm;
            #pragma unroll
            for (int r = 0; r < 8; r++) d[SMX(base + r * Ns)] = v[r];
        }
        __syncthreads();
        float2* t = s; s = d; d = t;
        Ns <<= 3;
    }
    const float angc2 = (float)DIR * 6.283185307179586f / 8192.0f;
    #pragma unroll
    for (int it = 0; it < 8; it++) {
        int j = tid + it * 512;
        float c, sn;
        __sincosf(angc2 * (float)j, &sn, &c);
        float2 v0 = s[SMX(j)];
        float2 v1 = cmul(s[SMX(j + 4096)], make_float2(c, sn));
        d[SMX(j)]        = make_float2(v0.x + v1.x, v0.y + v1.y);
        d[SMX(j + 4096)] = make_float2(v0.x - v1.x, v0.y - v1.y);
    }
    __syncthreads();
}

// ---------------------------------------------------------------------------
// bf16 split helpers
// ---------------------------------------------------------------------------
__device__ __forceinline__ uint32_t pkbf(float lo, float hi) {
    uint32_t r;
    asm("cvt.rn.bf16x2.f32 %0, %1, %2;" : "=r"(r) : "f"(hi), "f"(lo));
    return r;
}
__device__ __forceinline__ float bfhi(float x) {
    return __bfloat162float(__float2bfloat16_rn(x));
}

// ---------------------------------------------------------------------------
// Pre-pass P1: split x -> AH/AL bf16 planes (row-major [m][k], k pairs packed)
// ---------------------------------------------------------------------------
__global__ void __launch_bounds__(256)
split_x_kernel(const float* __restrict__ X) {
    int i = blockIdx.x * 256 + threadIdx.x;    // float4 index
    float4 v = *(const float4*)(X + (size_t)i * 4);
    float h0 = bfhi(v.x), h1 = bfhi(v.y), h2 = bfhi(v.z), h3 = bfhi(v.w);
    g_AHw[(size_t)i * 2]     = pkbf(h0, h1);
    g_AHw[(size_t)i * 2 + 1] = pkbf(h2, h3);
    g_ALw[(size_t)i * 2]     = pkbf(v.x - h0, v.y - h1);
    g_ALw[(size_t)i * 2 + 1] = pkbf(v.z - h2, v.w - h3);
}

// ---------------------------------------------------------------------------
// Pre-pass P2: split + transpose Mi [k][n] -> BH/BL [n][k] bf16 pairs
// ---------------------------------------------------------------------------
__global__ void __launch_bounds__(256)
split_b_kernel(const float* __restrict__ Mi) {
    int idx = blockIdx.x * 256 + threadIdx.x;  // 768*384
    int n  = idx % DIM;
    int kp = idx / DIM;                        // k pair 0..383
    float v0 = Mi[(size_t)(2 * kp) * DIM + n];
    float v1 = Mi[(size_t)(2 * kp + 1) * DIM + n];
    float h0 = bfhi(v0), h1 = bfhi(v1);
    g_BHw[(size_t)n * (DIM / 2) + kp] = pkbf(h0, h1);
    g_BLw[(size_t)n * (DIM / 2) + kp] = pkbf(v0 - h0, v1 - h1);
}

// ---------------------------------------------------------------------------
// Kernel 1: filter prep. One CTA per output channel d.
// ---------------------------------------------------------------------------
__global__ void __launch_bounds__(512, 1)
filter_kernel(const float* __restrict__ phi, const float* __restrict__ Mf) {
    extern __shared__ float2 fb[];
    float2* A  = fb;
    float2* Bu = fb + FFT_BUF;
    __shared__ float mf[NK];

    const int tid = threadIdx.x;
    const int d   = blockIdx.x;
    if (tid < NK) mf[tid] = Mf[tid * DIM + d];
    __syncthreads();

    const float sc = 2.0f / 8192.0f;
    #pragma unroll 1
    for (int it = 0; it < 16; it++) {
        int i = tid + it * 512;
        float s = 0.0f;
        if (i < HALF) {
            const float* pr = phi + (size_t)i * (2 * NK);
            #pragma unroll
            for (int k = 0; k < NK; k++) s += pr[k] * mf[k];
        }
        A[SMX(i)] = make_float2(s * sc, 0.0f);
    }
    __syncthreads();

    fft8192<-1>(A, Bu, tid);

    float2* vsd = g_VS + ((size_t)d << 13);
    #pragma unroll 1
    for (int it = 0; it < 16; it++) {
        int i = tid + it * 512;
        vsd[i] = Bu[SMX(i)];
    }
}

// ---------------------------------------------------------------------------
// GEMM: pure bf16 pipelined kernel. CTA 128Mx128N, 72 K-chunks of 32
// (3 passes x 24), 4-stage cp.async ring, ldmatrix fragments, 80B row pitch.
// ---------------------------------------------------------------------------
__device__ __forceinline__ uint32_t smem_u32(const void* p) {
    uint32_t a;
    asm("{ .reg .u64 t; cvta.to.shared.u64 t, %1; cvt.u32.u64 %0, t; }" : "=r"(a) : "l"(p));
    return a;
}
__device__ __forceinline__ void cpa16(uint32_t dst, const void* src) {
    asm volatile("cp.async.cg.shared.global [%0], [%1], 16;" :: "r"(dst), "l"(src));
}
__device__ __forceinline__ void ldsm4(uint32_t* r, uint32_t addr) {
    asm volatile("ldmatrix.sync.aligned.m8n8.x4.shared.b16 {%0,%1,%2,%3}, [%4];"
                 : "=r"(r[0]), "=r"(r[1]), "=r"(r[2]), "=r"(r[3]) : "r"(addr));
}
__device__ __forceinline__ void mma16(float4& d,
                                      uint32_t a0, uint32_t a1, uint32_t a2, uint32_t a3,
                                      uint32_t b0, uint32_t b1) {
    asm volatile(
        "mma.sync.aligned.m16n8k16.row.col.f32.bf16.bf16.f32 "
        "{%0,%1,%2,%3}, {%4,%5,%6,%7}, {%8,%9}, {%0,%1,%2,%3};"
        : "+f"(d.x), "+f"(d.y), "+f"(d.z), "+f"(d.w)
        : "r"(a0), "r"(a1), "r"(a2), "r"(a3), "r"(b0), "r"(b1));
}

#define APITCH 80                     // bytes per 32-k row (64B data + 16B pad)
#define STG_B  (128 * APITCH)        // 10240: one matrix per stage
#define STG_BYTES (2 * STG_B)        // 20480: A + B
#define GEMM_DYN_BYTES (4 * STG_BYTES)   // 81920, 4 stages
#define NCHUNK 72

// one thread's share of a chunk's cp.async: 1 row, 2x16B for A and B each
__device__ __forceinline__ void gemm_issue(int c, uint32_t sbase, int tid,
                                           int l0, int n0) {
    int pass = c / 24;
    int kc   = c - pass * 24;
    const uint32_t* Aw = (pass < 2) ? g_AHw : g_ALw;
    const uint32_t* Bw = (pass == 1) ? g_BLw : g_BHw;
    uint32_t st = sbase + (uint32_t)(c & 3) * STG_BYTES;
    int row = tid >> 1;
    int sg  = (tid & 1) * 2;
    const uint32_t* asrc = Aw + (size_t)(l0 + row) * (DIM / 2) + kc * 16 + sg * 4;
    uint32_t adst = st + (uint32_t)(row * APITCH + sg * 16);
    cpa16(adst, asrc);
    cpa16(adst + 16, asrc + 4);
    const uint32_t* bsrc = Bw + (size_t)(n0 + row) * (DIM / 2) + kc * 16 + sg * 4;
    uint32_t bdst = st + STG_B + (uint32_t)(row * APITCH + sg * 16);
    cpa16(bdst, bsrc);
    cpa16(bdst + 16, bsrc + 4);
    asm volatile("cp.async.commit_group;" ::: "memory");
}

__global__ void __launch_bounds__(256, 2)
gemm_kernel(int dummy) {
    extern __shared__ uint8_t smem_raw[];
    const uint32_t sbase = smem_u32(smem_raw);

    const int tid  = threadIdx.x;
    const int wid  = tid >> 5;
    const int lane = tid & 31;
    const int g    = lane >> 2;
    const int tig  = lane & 3;
    const int m0   = (wid & 1) * 64;
    const int nw0  = (wid >> 1) * 32;

    const int n0 = blockIdx.x * 128;
    const int l0 = blockIdx.y * 128;

    // prologue: fill 3 stages
    gemm_issue(0, sbase, tid, l0, n0);
    gemm_issue(1, sbase, tid, l0, n0);
    gemm_issue(2, sbase, tid, l0, n0);

    float4 acc[4][4];
    #pragma unroll
    for (int mt = 0; mt < 4; mt++)
        #pragma unroll
        for (int nt = 0; nt < 4; nt++)
            acc[mt][nt] = make_float4(0.f, 0.f, 0.f, 0.f);

    // fragment address components (stage-relative)
    const uint32_t aoff = (uint32_t)((m0 + (lane & 15)) * APITCH + (lane >> 4) * 16);
    const uint32_t boff = (uint32_t)(STG_B
                        + (nw0 + (lane & 7) + ((lane >> 4) << 3)) * APITCH
                        + ((lane >> 3) & 1) * 16);

    #pragma unroll 1
    for (int c = 0; c < NCHUNK; c++) {
        asm volatile("cp.async.wait_group 2;" ::: "memory");
        __syncthreads();
        if (c < NCHUNK - 3) gemm_issue(c + 3, sbase, tid, l0, n0);

        const uint32_t st = sbase + (uint32_t)(c & 3) * STG_BYTES;
        #pragma unroll
        for (int ks = 0; ks < 2; ks++) {
            uint32_t a[4][4];
            #pragma unroll
            for (int mt = 0; mt < 4; mt++)
                ldsm4(a[mt], st + aoff + (uint32_t)(mt * 16 * APITCH + ks * 32));
            uint32_t b[2][4];
            #pragma unroll
            for (int nh = 0; nh < 2; nh++)
                ldsm4(b[nh], st + boff + (uint32_t)(nh * 16 * APITCH + ks * 32));
            #pragma unroll
            for (int mt = 0; mt < 4; mt++)
                #pragma unroll
                for (int nt = 0; nt < 4; nt++)
                    mma16(acc[mt][nt], a[mt][0], a[mt][1], a[mt][2], a[mt][3],
                          b[nt >> 1][(nt & 1) * 2], b[nt >> 1][(nt & 1) * 2 + 1]);
        }
    }

    // epilogue: write transposed -> g_XT[b, d, l]
    const int b    = l0 >> 13;
    const int lloc = l0 & (SEQ - 1);
    #pragma unroll
    for (int mt = 0; mt < 4; mt++) {
        const int lbase = lloc + m0 + mt * 16 + g;
        #pragma unroll
        for (int nt = 0; nt < 4; nt++) {
            const int d0 = n0 + nw0 + nt * 8 + 2 * tig;
            float4 cc = acc[mt][nt];
            float* pa = g_XT + (((size_t)(b * DIM + d0)) << 13) + lbase;
            float* pb = g_XT + (((size_t)(b * DIM + d0 + 1)) << 13) + lbase;
            pa[0] = cc.x; pb[0] = cc.y;
            pa[8] = cc.z; pb[8] = cc.w;
        }
    }
}

// ---------------------------------------------------------------------------
// Kernel 3: per-(b,d) FFT convolution, in place on g_XT rows.
// ---------------------------------------------------------------------------
__global__ void __launch_bounds__(512, 1)
conv_kernel() {
    extern __shared__ float2 fb[];
    float2* A  = fb;
    float2* Bu = fb + FFT_BUF;

    const int tid = threadIdx.x;
    const int d   = blockIdx.x >> 2;
    const int b   = blockIdx.x & 3;

    float2* row = (float2*)(g_XT + (((size_t)(b * DIM + d)) << 13));

    #pragma unroll 1
    for (int it = 0; it < 16; it++) {
        int i = tid + it * 512;
        A[SMX(i)] = (i < HALF) ? row[i] : make_float2(0.0f, 0.0f);
    }
    __syncthreads();

    fft8192<-1>(A, Bu, tid);

    const float2* vs = g_VS + ((size_t)d << 13);
    #pragma unroll 1
    for (int it = 0; it < 16; it++) {
        int i = tid + it * 512;
        Bu[SMX(i)] = cmul(Bu[SMX(i)], vs[i]);
    }
    __syncthreads();

    fft8192<1>(Bu, A, tid);

    #pragma unroll 1
    for (int it = 0; it < 8; it++) {
        int i = tid + it * 512;
        row[i] = A[SMX(i)];                // (Re,Im) = (out[2m], out[2m+1])
    }
}

// ---------------------------------------------------------------------------
// Kernel 4: transpose g_XT (B,D,L) -> out (B,L,D)
// ---------------------------------------------------------------------------
__global__ void __launch_bounds__(256, 4)
transpose_kernel(float* __restrict__ out) {
    __shared__ float t[32][33];
    const int b  = blockIdx.z;
    const int l0 = blockIdx.x * 32;
    const int d0 = blockIdx.y * 32;
    const int tx = threadIdx.x, ty = threadIdx.y;   // 32 x 8

    const float* src = g_XT + (size_t)b * DIM * SEQ;
    #pragma unroll
    for (int i = 0; i < 4; i++)
        t[ty + i * 8][tx] = src[(size_t)(d0 + ty + i * 8) * SEQ + l0 + tx];
    __syncthreads();
    float* dst = out + (size_t)b * SEQ * DIM;
    #pragma unroll
    for (int i = 0; i < 4; i++)
        dst[(size_t)(l0 + ty + i * 8) * DIM + d0 + tx] = t[tx][ty + i * 8];
}

// ---------------------------------------------------------------------------
// launch
// ---------------------------------------------------------------------------
extern "C" void kernel_launch(void* const* d_in, const int* in_sizes, int n_in,
                              void* d_out, int out_size) {
    const float* x   = (const float*)d_in[0];
    const float* phi = (const float*)d_in[1];
    const float* Mi  = (const float*)d_in[2];
    const float* Mf  = (const float*)d_in[3];
    float* out = (float*)d_out;

    cudaFuncSetAttribute(filter_kernel, cudaFuncAttributeMaxDynamicSharedMemorySize, FFT_SMEM_BYTES);
    cudaFuncSetAttribute(conv_kernel,   cudaFuncAttributeMaxDynamicSharedMemorySize, FFT_SMEM_BYTES);
    cudaFuncSetAttribute(gemm_kernel,   cudaFuncAttributeMaxDynamicSharedMemorySize, GEMM_DYN_BYTES);

    split_x_kernel<<<(BATCH * SEQ * DIM / 4) / 256, 256>>>(x);
    split_b_kernel<<<(DIM * DIM / 2) / 256, 256>>>(Mi);
    filter_kernel<<<DIM, 512, FFT_SMEM_BYTES>>>(phi, Mf);
    gemm_kernel<<<dim3(DIM / 128, (BATCH * SEQ) / 128), 256, GEMM_DYN_BYTES>>>(0);
    conv_kernel<<<BATCH * DIM, 512, FFT_SMEM_BYTES>>>();
    transpose_kernel<<<dim3(SEQ / 32, DIM / 32, BATCH), dim3(32, 8)>>>(out);
}